// round 8
// baseline (speedup 1.0000x reference)
#include <cuda_runtime.h>
#include <cuda_bf16.h>

#define PB 64      // preds per block
#define TB 128     // targets per block (4 per lane)
#define EPS 1e-6f
#define MAXC 16
#define PSTRIDE 65 // 65 % 32 == 1 -> distinct labels hit distinct banks

__device__ __forceinline__ float frcp_fast(float x) {
    float r;
    asm("rcp.approx.f32 %0, %1;" : "=f"(r) : "f"(x));
    return r;
}

__global__ __launch_bounds__(256, 5)
void hungarian_cost_kernel(
    const float* __restrict__ logits,   // [N, C]
    const float* __restrict__ pboxes,   // [N, 4] cxcywh
    const int*   __restrict__ tlabels,  // [T]
    const float* __restrict__ tboxes,   // [T, 4] cxcywh
    float* __restrict__ out,            // [N, T]
    int C, int T)
{
    // pred row: [x0,y0,x1,y1][2w,2h,paE,pad]  -> exactly 2x LDS.128
    __shared__ __align__(16) float s_pred[PB][8];
    // flat transposed prob table: s_probT[c*PSTRIDE + p] = 2 - softmax[c]
    __shared__ float s_probT[11 * PSTRIDE];

    const int tid    = threadIdx.x;
    const int lane   = tid & 31;
    const int wrp    = tid >> 5;
    const int t_base = blockIdx.x * TB;
    const int n_base = blockIdx.y * PB;

    // ---- prolog: per-pred softmax + box precompute (threads 0..63) ----
    if (tid < PB) {
        const int n = n_base + tid;
        const float* lg = logits + (size_t)n * C;
        float mx = -1e30f;
        #pragma unroll 4
        for (int c = 0; c < C; c++) mx = fmaxf(mx, lg[c]);
        float e[MAXC];
        float s = 0.0f;
        #pragma unroll 4
        for (int c = 0; c < C; c++) { e[c] = __expf(lg[c] - mx); s += e[c]; }
        float inv = __frcp_rn(s);
        #pragma unroll 4
        for (int c = 0; c < C; c++) s_probT[c * PSTRIDE + tid] = 2.0f - e[c] * inv;

        float4 b = reinterpret_cast<const float4*>(pboxes)[n];
        float* row = s_pred[tid];
        row[0] = b.x - 0.5f * b.z;
        row[1] = b.y - 0.5f * b.w;
        row[2] = b.x + 0.5f * b.z;
        row[3] = b.y + 0.5f * b.w;
        row[4] = 2.0f * b.z;
        row[5] = 2.0f * b.w;
        row[6] = b.z * b.w + EPS;
        row[7] = 0.0f;
    }

    // ---- per-lane: 4 targets, slim state: corners + area (5 regs/target) ----
    const int t0 = t_base + lane * 4;
    const float4* tb4 = reinterpret_cast<const float4*>(tboxes);
    float4 b0 = tb4[t0 + 0], b1 = tb4[t0 + 1], b2 = tb4[t0 + 2], b3 = tb4[t0 + 3];
    int4 tl4 = reinterpret_cast<const int4*>(tlabels)[t0 >> 2];

    float tx0[4], ty0[4], tx1[4], ty1[4], ta[4];
    {
        float cx[4] = {b0.x, b1.x, b2.x, b3.x};
        float cy[4] = {b0.y, b1.y, b2.y, b3.y};
        float w [4] = {b0.z, b1.z, b2.z, b3.z};
        float h [4] = {b0.w, b1.w, b2.w, b3.w};
        #pragma unroll
        for (int j = 0; j < 4; j++) {
            tx0[j] = fmaf(-0.5f, w[j], cx[j]);
            ty0[j] = fmaf(-0.5f, h[j], cy[j]);
            tx1[j] = fmaf( 0.5f, w[j], cx[j]);
            ty1[j] = fmaf( 0.5f, h[j], cy[j]);
            ta[j]  = w[j] * h[j];
        }
    }

    __syncthreads();

    // gather offsets: 32-bit ints, hot loop indexes with +i immediates
    const int p_first = wrp * (PB / 8);
    int gofs[4];
    {
        const int tl[4] = {tl4.x, tl4.y, tl4.z, tl4.w};
        #pragma unroll
        for (int j = 0; j < 4; j++)
            gofs[j] = tl[j] * PSTRIDE + p_first;
    }

    float* orow = out + (size_t)(n_base + p_first) * T + t_base + lane * 4;

    // ---- main loop: warp handles 8 contiguous preds ----
    #pragma unroll
    for (int i = 0; i < PB / 8; i++) {
        const float* rowp = s_pred[p_first + i];
        const float4 a0 = reinterpret_cast<const float4*>(rowp)[0]; // x0,y0,x1,y1
        const float4 a1 = reinterpret_cast<const float4*>(rowp)[1]; // 2w,2h,paE,-
        const float px0 = a0.x, py0 = a0.y, px1 = a0.z, py1 = a0.w;
        const float p2w = a1.x, p2h = a1.y, paE = a1.z;

        float o[4];
        #pragma unroll
        for (int j = 0; j < 4; j++) {
            // corner diffs feed BOTH the L1 and the enclosing box
            float dx0 = px0 - tx0[j], dx1 = px1 - tx1[j];
            float dy0 = py0 - ty0[j], dy1 = py1 - ty1[j];
            float sx = dx0 + dx1, dX = dx1 - dx0;   // 2*(pcx-tcx), pw-tw
            float sy = dy0 + dy1, dY = dy1 - dy0;
            float habs = fabsf(sx) + fabsf(sy);
            float dabs = fabsf(dX) + fabsf(dY);
            float base = fmaf(2.5f, habs, fmaf(5.0f, dabs, s_probT[gofs[j] + i]));
            // raw intersection extents
            float iwr = fminf(px1, tx1[j]) - fmaxf(px0, tx0[j]);
            float ihr = fminf(py1, ty1[j]) - fmaxf(py0, ty0[j]);
            float inter = fmaxf(iwr, 0.0f) * fmaxf(ihr, 0.0f);
            // enclosing box: pw+tw = p2w - dX  (exact)
            float cw = (p2w - dX) - iwr;
            float ch = (p2h - dY) - ihr;
            float d1 = (paE + ta[j]) - inter;       // union + eps
            float d2 = fmaf(cw, ch, EPS);           // area_c + eps
            float r  = frcp_fast(d1 * d2);
            float t  = fmaf(inter, d2, d1 * d1);
            o[j] = fmaf(-2.0f * r, t, base);
        }
        reinterpret_cast<float4*>(orow + (size_t)i * T)[0] =
            make_float4(o[0], o[1], o[2], o[3]);
    }
}

extern "C" void kernel_launch(void* const* d_in, const int* in_sizes, int n_in,
                              void* d_out, int out_size)
{
    const float* logits  = (const float*)d_in[0];   // [B*Q, C] fp32
    const float* pboxes  = (const float*)d_in[1];   // [B*Q, 4] fp32
    const int*   tlabels = (const int*)  d_in[2];   // [T] int32
    const float* tboxes  = (const float*)d_in[3];   // [T, 4] fp32

    const int T = in_sizes[2];          // 3200
    const int N = in_sizes[1] / 4;      // 9600
    const int C = in_sizes[0] / N;      // 11

    dim3 grid(T / TB, N / PB);          // (25, 150)
    hungarian_cost_kernel<<<grid, 256>>>(logits, pboxes, tlabels, tboxes,
                                         (float*)d_out, C, T);
}

// round 9
// speedup vs baseline: 1.1298x; 1.1298x over previous
#include <cuda_runtime.h>
#include <cuda_bf16.h>

#define PB 128     // preds per block
#define TB 128     // targets per block (4 per lane)
#define EPS 1e-6f
#define MAXC 16
#define PSTRIDE 129 // 129 % 32 == 1 -> distinct labels hit distinct banks

__device__ __forceinline__ float frcp_fast(float x) {
    float r;
    asm("rcp.approx.f32 %0, %1;" : "=f"(r) : "f"(x));
    return r;
}

// TT/CC: compile-time T and C (0 = use runtime value)
template<int TT, int CC>
__global__ __launch_bounds__(256, 4)
void hungarian_cost_kernel(
    const float* __restrict__ logits,   // [N, C]
    const float* __restrict__ pboxes,   // [N, 4] cxcywh
    const int*   __restrict__ tlabels,  // [T]
    const float* __restrict__ tboxes,   // [T, 4] cxcywh
    float* __restrict__ out,            // [N, T]
    int Crt, int Trt)
{
    const int T = TT ? TT : Trt;
    const int C = CC ? CC : Crt;

    // pred row: [cx,cy,w,h][x0,y0,x1,y1][paE,pad,pad,pad]
    __shared__ __align__(16) float s_pred[PB][12];
    // transposed prob table: s_probT[c*PSTRIDE + p] = 2 - softmax(logits[p])[c]
    __shared__ float s_probT[MAXC * PSTRIDE];

    const int tid    = threadIdx.x;
    const int lane   = tid & 31;
    const int wrp    = tid >> 5;
    const int t_base = blockIdx.x * TB;
    const int n_base = blockIdx.y * PB;

    // ---- prolog: per-pred softmax + box precompute (threads 0..127) ----
    if (tid < PB) {
        const int n = n_base + tid;
        const float* lg = logits + (size_t)n * C;
        float mx = -1e30f;
        #pragma unroll 4
        for (int c = 0; c < C; c++) mx = fmaxf(mx, lg[c]);
        float e[MAXC];
        float s = 0.0f;
        #pragma unroll 4
        for (int c = 0; c < C; c++) { e[c] = __expf(lg[c] - mx); s += e[c]; }
        float inv = __frcp_rn(s);
        #pragma unroll 4
        for (int c = 0; c < C; c++) s_probT[c * PSTRIDE + tid] = 2.0f - e[c] * inv;

        float4 b = reinterpret_cast<const float4*>(pboxes)[n];
        float* row = s_pred[tid];
        row[0] = b.x;  row[1] = b.y;  row[2] = b.z;  row[3] = b.w;
        row[4] = b.x - 0.5f * b.z;
        row[5] = b.y - 0.5f * b.w;
        row[6] = b.x + 0.5f * b.z;
        row[7] = b.y + 0.5f * b.w;
        row[8] = b.z * b.w + EPS;
    }

    // ---- per-lane: 4 targets in registers (once per block) ----
    const int t0 = t_base + lane * 4;
    const float4* tb4 = reinterpret_cast<const float4*>(tboxes);
    float4 b0 = tb4[t0 + 0], b1 = tb4[t0 + 1], b2 = tb4[t0 + 2], b3 = tb4[t0 + 3];
    int4 tl4 = reinterpret_cast<const int4*>(tlabels)[t0 >> 2];

    float tcx[4] = {b0.x, b1.x, b2.x, b3.x};
    float tcy[4] = {b0.y, b1.y, b2.y, b3.y};
    float twd[4] = {b0.z, b1.z, b2.z, b3.z};
    float tht[4] = {b0.w, b1.w, b2.w, b3.w};
    float tx0[4], ty0[4], tx1[4], ty1[4], ta[4];
    #pragma unroll
    for (int j = 0; j < 4; j++) {
        tx0[j] = fmaf(-0.5f, twd[j], tcx[j]);
        ty0[j] = fmaf(-0.5f, tht[j], tcy[j]);
        tx1[j] = fmaf( 0.5f, twd[j], tcx[j]);
        ty1[j] = fmaf( 0.5f, tht[j], tcy[j]);
        ta[j]  = twd[j] * tht[j];
    }

    __syncthreads();

    // gather offsets: 32-bit ints, hot loop indexes with +i immediates
    const int p_first = wrp * (PB / 8);
    int gofs[4];
    {
        const int tl[4] = {tl4.x, tl4.y, tl4.z, tl4.w};
        #pragma unroll
        for (int j = 0; j < 4; j++)
            gofs[j] = tl[j] * PSTRIDE + p_first;
    }

    float* orow = out + (size_t)(n_base + p_first) * T + t_base + lane * 4;

    // ---- main loop: warp handles 16 contiguous preds ----
    #pragma unroll 4
    for (int i = 0; i < PB / 8; i++) {
        const float* rowp = s_pred[p_first + i];
        const float4 a0 = reinterpret_cast<const float4*>(rowp)[0]; // cx,cy,w,h
        const float4 a1 = reinterpret_cast<const float4*>(rowp)[1]; // x0,y0,x1,y1
        const float paE = rowp[8];
        const float pcx = a0.x, pcy = a0.y, pw = a0.z, ph = a0.w;
        const float px0 = a1.x, py0 = a1.y, px1 = a1.z, py1 = a1.w;

        float o[4];
        #pragma unroll
        for (int j = 0; j < 4; j++) {
            // L1 (abs folded into FADD source modifiers)
            float dcx = pcx - tcx[j], dcy = pcy - tcy[j];
            float dw  = pw  - twd[j], dh  = ph  - tht[j];
            float h1 = fabsf(dcx) + fabsf(dcy);
            float h2 = fabsf(dw)  + fabsf(dh);
            // raw intersection extents (may be negative)
            float iwr = fminf(px1, tx1[j]) - fmaxf(px0, tx0[j]);
            float ihr = fminf(py1, ty1[j]) - fmaxf(py0, ty0[j]);
            float inter = fmaxf(iwr, 0.0f) * fmaxf(ihr, 0.0f);
            // enclosing box via exact identity min+max = sum
            float cw = (pw + twd[j]) - iwr;
            float ch = (ph + tht[j]) - ihr;
            float d1 = (paE + ta[j]) - inter;     // union + eps
            float d2 = fmaf(cw, ch, EPS);         // area_c + eps
            float r  = frcp_fast(d1 * d2);
            // C = (2-prob) + 5*l1 - 2*(inter/d1 + d1/d2)
            float t    = fmaf(inter, d2, d1 * d1);
            float base = fmaf(5.0f, h1, fmaf(5.0f, h2, s_probT[gofs[j] + i]));
            o[j] = fmaf(-2.0f * r, t, base);
        }
        reinterpret_cast<float4*>(orow + (size_t)i * T)[0] =
            make_float4(o[0], o[1], o[2], o[3]);
    }
}

extern "C" void kernel_launch(void* const* d_in, const int* in_sizes, int n_in,
                              void* d_out, int out_size)
{
    const float* logits  = (const float*)d_in[0];   // [B*Q, C] fp32
    const float* pboxes  = (const float*)d_in[1];   // [B*Q, 4] fp32
    const int*   tlabels = (const int*)  d_in[2];   // [T] int32
    const float* tboxes  = (const float*)d_in[3];   // [T, 4] fp32

    const int T = in_sizes[2];          // 3200
    const int N = in_sizes[1] / 4;      // 9600
    const int C = in_sizes[0] / N;      // 11

    dim3 grid(T / TB, N / PB);          // (25, 75) for the bench shape
    if (T == 3200 && C == 11) {
        hungarian_cost_kernel<3200, 11><<<grid, 256>>>(
            logits, pboxes, tlabels, tboxes, (float*)d_out, C, T);
    } else {
        hungarian_cost_kernel<0, 0><<<grid, 256>>>(
            logits, pboxes, tlabels, tboxes, (float*)d_out, C, T);
    }
}

// round 12
// speedup vs baseline: 1.1798x; 1.0442x over previous
#include <cuda_runtime.h>
#include <cuda_bf16.h>

#define PB 128     // preds per block
#define TB 128     // targets per block (4 per lane)
#define EPS 1e-6f
#define MAXC 16
#define PSTRIDE 129 // 129 % 32 == 1 -> distinct labels hit distinct banks

__device__ __forceinline__ float frcp_fast(float x) {
    float r;
    asm("rcp.approx.f32 %0, %1;" : "=f"(r) : "f"(x));
    return r;
}

// TT/CC: compile-time T and C (0 = use runtime value)
template<int TT, int CC>
__global__ __launch_bounds__(256, 4)
void hungarian_cost_kernel(
    const float* __restrict__ logits,   // [N, C]
    const float* __restrict__ pboxes,   // [N, 4] cxcywh
    const int*   __restrict__ tlabels,  // [T]
    const float* __restrict__ tboxes,   // [T, 4] cxcywh
    float* __restrict__ out,            // [N, T]
    int Crt, int Trt)
{
    const int T = TT ? TT : Trt;
    const int C = CC ? CC : Crt;

    // flat pred tile: 12 floats per pred: [cx,cy,w,h][x0,y0,x1,y1][paE,-,-,-]
    __shared__ __align__(16) float s_pred[PB * 12];
    // transposed prob table: s_probT[c*PSTRIDE + p] = 2 - softmax(logits[p])[c]
    __shared__ float s_probT[MAXC * PSTRIDE];

    const int tid    = threadIdx.x;
    const int lane   = tid & 31;
    const int wrp    = tid >> 5;
    const int t_base = blockIdx.x * TB;
    const int n_base = blockIdx.y * PB;

    // ---- prolog: per-pred softmax + box precompute (threads 0..127) ----
    if (tid < PB) {
        const int n = n_base + tid;
        const float* lg = logits + (size_t)n * C;
        float mx = -1e30f;
        #pragma unroll 4
        for (int c = 0; c < C; c++) mx = fmaxf(mx, lg[c]);
        float e[MAXC];
        float s = 0.0f;
        #pragma unroll 4
        for (int c = 0; c < C; c++) { e[c] = __expf(lg[c] - mx); s += e[c]; }
        float inv = __frcp_rn(s);
        #pragma unroll 4
        for (int c = 0; c < C; c++) s_probT[c * PSTRIDE + tid] = 2.0f - e[c] * inv;

        float4 b = reinterpret_cast<const float4*>(pboxes)[n];
        float* row = &s_pred[tid * 12];
        row[0] = b.x;  row[1] = b.y;  row[2] = b.z;  row[3] = b.w;
        row[4] = b.x - 0.5f * b.z;
        row[5] = b.y - 0.5f * b.w;
        row[6] = b.x + 0.5f * b.z;
        row[7] = b.y + 0.5f * b.w;
        row[8] = b.z * b.w + EPS;
    }

    // ---- per-lane: 4 targets in registers (once per block) ----
    const int t0 = t_base + lane * 4;
    const float4* tb4 = reinterpret_cast<const float4*>(tboxes);
    float4 b0 = tb4[t0 + 0], b1 = tb4[t0 + 1], b2 = tb4[t0 + 2], b3 = tb4[t0 + 3];
    int4 tl4 = reinterpret_cast<const int4*>(tlabels)[t0 >> 2];

    float tcx[4] = {b0.x, b1.x, b2.x, b3.x};
    float tcy[4] = {b0.y, b1.y, b2.y, b3.y};
    float twd[4] = {b0.z, b1.z, b2.z, b3.z};
    float tht[4] = {b0.w, b1.w, b2.w, b3.w};
    float tx0[4], ty0[4], tx1[4], ty1[4], ta[4];
    #pragma unroll
    for (int j = 0; j < 4; j++) {
        tx0[j] = fmaf(-0.5f, twd[j], tcx[j]);
        ty0[j] = fmaf(-0.5f, tht[j], tcy[j]);
        tx1[j] = fmaf( 0.5f, twd[j], tcx[j]);
        ty1[j] = fmaf( 0.5f, tht[j], tcy[j]);
        ta[j]  = twd[j] * tht[j];
    }

    __syncthreads();

    // ---- precomputed base pointers: hot loop uses [R + imm] only ----
    const int p_first = wrp * (PB / 8);
    const float* gp0 = &s_probT[tl4.x * PSTRIDE + p_first];
    const float* gp1 = &s_probT[tl4.y * PSTRIDE + p_first];
    const float* gp2 = &s_probT[tl4.z * PSTRIDE + p_first];
    const float* gp3 = &s_probT[tl4.w * PSTRIDE + p_first];
    const float4* pbase = reinterpret_cast<const float4*>(&s_pred[p_first * 12]);
    const float*  pbasef = &s_pred[p_first * 12];
    float4* obase = reinterpret_cast<float4*>(
        out + (size_t)(n_base + p_first) * T + t_base + lane * 4);
    const int ostride4 = T >> 2;   // compile-time when TT != 0

    // ---- main loop: warp handles 16 contiguous preds ----
    #pragma unroll 8
    for (int i = 0; i < PB / 8; i++) {
        const float4 a0 = pbase[i * 3 + 0];      // cx,cy,w,h
        const float4 a1 = pbase[i * 3 + 1];      // x0,y0,x1,y1
        const float paE = pbasef[i * 12 + 8];
        const float pcx = a0.x, pcy = a0.y, pw = a0.z, ph = a0.w;
        const float px0 = a1.x, py0 = a1.y, px1 = a1.z, py1 = a1.w;

        const float pv[4] = {gp0[i], gp1[i], gp2[i], gp3[i]};

        float4 o;
        float* op = reinterpret_cast<float*>(&o);
        #pragma unroll
        for (int j = 0; j < 4; j++) {
            // L1 (abs folded into FADD source modifiers)
            float dcx = pcx - tcx[j], dcy = pcy - tcy[j];
            float dw  = pw  - twd[j], dh  = ph  - tht[j];
            float h1 = fabsf(dcx) + fabsf(dcy);
            float h2 = fabsf(dw)  + fabsf(dh);
            // raw intersection extents (may be negative)
            float iwr = fminf(px1, tx1[j]) - fmaxf(px0, tx0[j]);
            float ihr = fminf(py1, ty1[j]) - fmaxf(py0, ty0[j]);
            float inter = fmaxf(iwr, 0.0f) * fmaxf(ihr, 0.0f);
            // enclosing box via exact identity min+max = sum
            float cw = (pw + twd[j]) - iwr;
            float ch = (ph + tht[j]) - ihr;
            float d1 = (paE + ta[j]) - inter;     // union + eps
            float d2 = fmaf(cw, ch, EPS);         // area_c + eps
            float r  = frcp_fast(d1 * d2);
            // C = (2-prob) + 5*l1 - 2*(inter/d1 + d1/d2)
            float t    = fmaf(inter, d2, d1 * d1);
            float base = fmaf(5.0f, h1, fmaf(5.0f, h2, pv[j]));
            op[j] = fmaf(-2.0f * r, t, base);
        }
        obase[i * ostride4] = o;
    }
}

extern "C" void kernel_launch(void* const* d_in, const int* in_sizes, int n_in,
                              void* d_out, int out_size)
{
    const float* logits  = (const float*)d_in[0];   // [B*Q, C] fp32
    const float* pboxes  = (const float*)d_in[1];   // [B*Q, 4] fp32
    const int*   tlabels = (const int*)  d_in[2];   // [T] int32
    const float* tboxes  = (const float*)d_in[3];   // [T, 4] cxcywh

    const int T = in_sizes[2];          // 3200
    const int N = in_sizes[1] / 4;      // 9600
    const int C = in_sizes[0] / N;      // 11

    dim3 grid(T / TB, N / PB);          // (25, 75) for the bench shape
    if (T == 3200 && C == 11) {
        hungarian_cost_kernel<3200, 11><<<grid, 256>>>(
            logits, pboxes, tlabels, tboxes, (float*)d_out, C, T);
    } else {
        hungarian_cost_kernel<0, 0><<<grid, 256>>>(
            logits, pboxes, tlabels, tboxes, (float*)d_out, C, T);
    }
}